// round 1
// baseline (speedup 1.0000x reference)
#include <cuda_runtime.h>
#include <cstdint>

#define B_SZ  16
#define N_IN  6250
#define N_OUT 25000
#define CCH   64
#define SNB   9
#define NNZ   75000

// 16 * 25000 * 64 floats = 102.4 MB scratch for pooled features, layout [B][N_OUT][C]
__device__ float g_pooled[(size_t)B_SZ * N_OUT * CCH];

using u64 = unsigned long long;

__device__ __forceinline__ u64 ffma2(u64 a, u64 b, u64 c) {
    u64 d;
    asm("fma.rn.f32x2 %0, %1, %2, %3;" : "=l"(d) : "l"(a), "l"(b), "l"(c));
    return d;
}
__device__ __forceinline__ u64 dup2(float a) {
    u64 d;
    asm("mov.b64 %0, {%1, %1};" : "=l"(d) : "f"(a));
    return d;
}
__device__ __forceinline__ void unpack2(u64 v, float& lo, float& hi) {
    asm("mov.b64 {%0, %1}, %2;" : "=f"(lo), "=f"(hi) : "l"(v));
}

// ---------------------------------------------------------------------------
// Kernel 0: zero the pooled scratch
// ---------------------------------------------------------------------------
__global__ void zero_pooled() {
    const size_t total = (size_t)B_SZ * N_OUT * CCH / 4;
    float4 z = make_float4(0.f, 0.f, 0.f, 0.f);
    float4* p = reinterpret_cast<float4*>(g_pooled);
    for (size_t i = (size_t)blockIdx.x * blockDim.x + threadIdx.x; i < total;
         i += (size_t)gridDim.x * blockDim.x)
        p[i] = z;
}

// ---------------------------------------------------------------------------
// Kernel 1: sparse pool (gather cols, scale, scatter-add rows)
// One thread per (nnz entry, 4-channel group); loops over batch.
// Uses vector red.global.add.v4.f32 to quarter the atomic lane count.
// ---------------------------------------------------------------------------
__global__ void pool_kernel(const float* __restrict__ x,
                            const float* __restrict__ tv,
                            const int* __restrict__ tr,
                            const int* __restrict__ tc) {
    int t = blockIdx.x * blockDim.x + threadIdx.x;
    if (t >= NNZ * 16) return;
    int e  = t >> 4;
    int cg = t & 15;
    float v = __ldg(tv + e);
    int row = __ldg(tr + e);
    int col = __ldg(tc + e);
    const float4* xp = reinterpret_cast<const float4*>(x);
#pragma unroll
    for (int b = 0; b < B_SZ; b++) {
        float4 xv = xp[((size_t)b * N_IN + col) * 16 + cg];
        float* dst = g_pooled + ((size_t)b * N_OUT + row) * CCH + cg * 4;
        asm volatile("red.global.add.v4.f32 [%0], {%1, %2, %3, %4};"
                     :: "l"(dst), "f"(xv.x * v), "f"(xv.y * v),
                        "f"(xv.z * v), "f"(xv.w * v)
                     : "memory");
    }
}

// ---------------------------------------------------------------------------
// Kernel 2: fused spiral gather + GEMM (K=576 as 9 x 64) + bias + ELU
// CTA tile: 128 rows (n) x 64 cols for one batch b.
// 128 threads, 8x8 microtile held as 8x4 packed f32x2 accumulators.
// ---------------------------------------------------------------------------
__global__ __launch_bounds__(128, 4) void spiral_gemm(
    const int*   __restrict__ sp,    // [N_OUT, 9]
    const float* __restrict__ W,     // [576, 64]
    const float* __restrict__ bias,  // [64]
    float*       __restrict__ out)   // [B, N_OUT, 64]
{
    __shared__ __align__(16) float As[64][128];  // A^T tile: As[k][row] (32 KB)
    __shared__ __align__(16) float Ws[64][64];   // W s-slice: Ws[k][c]   (16 KB)

    const int b   = blockIdx.y;
    const int n0  = blockIdx.x * 128;
    const int tid = threadIdx.x;
    const int q   = tid & 15;   // row group
    const int p   = tid >> 4;   // col group (0..7)

    u64 acc[8][4];
#pragma unroll
    for (int r = 0; r < 8; r++)
#pragma unroll
        for (int j = 0; j < 4; j++) acc[r][j] = 0ULL;

    const float* pooledB = g_pooled + (size_t)b * N_OUT * CCH;
    const int myn = n0 + tid;
    const bool valid = (myn < N_OUT);

    for (int s = 0; s < SNB; s++) {
        // --- stage W slice: 64x64 floats, fully coalesced float4 ---
        {
            const float4* wsrc = reinterpret_cast<const float4*>(W + s * 64 * 64);
            float4* wdst = reinterpret_cast<float4*>(&Ws[0][0]);
#pragma unroll
            for (int j = 0; j < 8; j++) wdst[tid + 128 * j] = wsrc[tid + 128 * j];
        }
        // --- stage gathered A tile: one thread per output row ---
        {
            int idx = valid ? __ldg(sp + myn * SNB + s) : 0;
            const float4* asrc =
                reinterpret_cast<const float4*>(pooledB + (size_t)idx * CCH);
#pragma unroll
            for (int j = 0; j < 16; j++) {
                float4 v = asrc[j];
                As[4 * j + 0][tid] = v.x;
                As[4 * j + 1][tid] = v.y;
                As[4 * j + 2][tid] = v.z;
                As[4 * j + 3][tid] = v.w;
            }
        }
        __syncthreads();

        // --- mainloop: 64 k-steps, packed f32x2 FMAs ---
#pragma unroll 8
        for (int k = 0; k < 64; k++) {
            float4 a0 = *reinterpret_cast<const float4*>(&As[k][q * 4]);
            float4 a1 = *reinterpret_cast<const float4*>(&As[k][q * 4 + 64]);
            // packed column pairs straight out of SMEM (no mov needed)
            ulonglong2 w0 = *reinterpret_cast<const ulonglong2*>(&Ws[k][p * 4]);
            ulonglong2 w1 = *reinterpret_cast<const ulonglong2*>(&Ws[k][p * 4 + 32]);
            u64 A[8] = {dup2(a0.x), dup2(a0.y), dup2(a0.z), dup2(a0.w),
                        dup2(a1.x), dup2(a1.y), dup2(a1.z), dup2(a1.w)};
#pragma unroll
            for (int r = 0; r < 8; r++) {
                acc[r][0] = ffma2(A[r], w0.x, acc[r][0]);
                acc[r][1] = ffma2(A[r], w0.y, acc[r][1]);
                acc[r][2] = ffma2(A[r], w1.x, acc[r][2]);
                acc[r][3] = ffma2(A[r], w1.y, acc[r][3]);
            }
        }
        __syncthreads();
    }

    // --- epilogue: bias + ELU + store ---
    float bb[8];
#pragma unroll
    for (int j = 0; j < 4; j++) {
        bb[j]     = __ldg(bias + p * 4 + j);
        bb[4 + j] = __ldg(bias + p * 4 + 32 + j);
    }
#pragma unroll
    for (int r = 0; r < 8; r++) {
        int m = q * 4 + (r & 3) + ((r >> 2) * 64);
        int n = n0 + m;
        if (n >= N_OUT) continue;
        float v[8];
        unpack2(acc[r][0], v[0], v[1]);
        unpack2(acc[r][1], v[2], v[3]);
        unpack2(acc[r][2], v[4], v[5]);
        unpack2(acc[r][3], v[6], v[7]);
        float o[8];
#pragma unroll
        for (int j = 0; j < 8; j++) {
            float t = v[j] + bb[j];
            o[j] = (t > 0.f) ? t : expm1f(t);
        }
        float* dst = out + ((size_t)b * N_OUT + n) * CCH + p * 4;
        *reinterpret_cast<float4*>(dst)      = make_float4(o[0], o[1], o[2], o[3]);
        *reinterpret_cast<float4*>(dst + 32) = make_float4(o[4], o[5], o[6], o[7]);
    }
}

// ---------------------------------------------------------------------------
extern "C" void kernel_launch(void* const* d_in, const int* in_sizes, int n_in,
                              void* d_out, int out_size) {
    const float* x    = (const float*)d_in[0];  // [16, 6250, 64]
    const float* tv   = (const float*)d_in[1];  // [75000]
    const int*   tr   = (const int*)d_in[2];    // [75000]
    const int*   tc   = (const int*)d_in[3];    // [75000]
    const int*   sp   = (const int*)d_in[4];    // [25000, 9]
    const float* W    = (const float*)d_in[5];  // [576, 64]
    const float* bias = (const float*)d_in[6];  // [64]
    float* out = (float*)d_out;                 // [16, 25000, 64]

    zero_pooled<<<2048, 256>>>();
    pool_kernel<<<(NNZ * 16 + 255) / 256, 256>>>(x, tv, tr, tc);

    dim3 grid((N_OUT + 127) / 128, B_SZ);
    spiral_gemm<<<grid, 128>>>(sp, W, bias, out);
}

// round 3
// speedup vs baseline: 1.7662x; 1.7662x over previous
#include <cuda_runtime.h>
#include <cuda_bf16.h>
#include <cstdint>

#define B_SZ  16
#define N_IN  6250
#define N_OUT 25000
#define CCH   64
#define SNB   9
#define NNZ   75000

// fp32 pooled accumulator [B][N_OUT][64] = 102.4 MB
__device__ float g_pooled[(size_t)B_SZ * N_OUT * CCH];
// bf16 hi/lo split of pooled, 51.2 MB each
__device__ unsigned short g_pooled_hi[(size_t)B_SZ * N_OUT * CCH];
__device__ unsigned short g_pooled_lo[(size_t)B_SZ * N_OUT * CCH];
// transposed + split W: [9][n=64][k=64] bf16
__device__ unsigned short g_wt_hi[SNB * 64 * 64];
__device__ unsigned short g_wt_lo[SNB * 64 * 64];

// ---------------------------------------------------------------------------
// helpers
// ---------------------------------------------------------------------------
__device__ __forceinline__ uint32_t smem_u32(const void* p) {
    uint32_t a;
    asm("{ .reg .u64 t; cvta.to.shared.u64 t, %1; cvt.u32.u64 %0, t; }"
        : "=r"(a) : "l"(p));
    return a;
}
__device__ __forceinline__ void cp16(uint32_t dst, const void* src) {
    asm volatile("cp.async.cg.shared.global [%0], [%1], 16;"
                 :: "r"(dst), "l"(src) : "memory");
}
__device__ __forceinline__ void cp_commit() {
    asm volatile("cp.async.commit_group;" ::: "memory");
}
template <int N>
__device__ __forceinline__ void cp_wait() {
    asm volatile("cp.async.wait_group %0;" :: "n"(N) : "memory");
}
__device__ __forceinline__ void ldm4(uint32_t* r, uint32_t addr) {
    asm volatile("ldmatrix.sync.aligned.m8n8.x4.shared.b16 {%0,%1,%2,%3}, [%4];"
                 : "=r"(r[0]), "=r"(r[1]), "=r"(r[2]), "=r"(r[3])
                 : "r"(addr));
}
__device__ __forceinline__ void mma16816(float* d, const uint32_t* a,
                                         const uint32_t* b) {
    asm volatile(
        "mma.sync.aligned.m16n8k16.row.col.f32.bf16.bf16.f32 "
        "{%0,%1,%2,%3},{%4,%5,%6,%7},{%8,%9},{%0,%1,%2,%3};"
        : "+f"(d[0]), "+f"(d[1]), "+f"(d[2]), "+f"(d[3])
        : "r"(a[0]), "r"(a[1]), "r"(a[2]), "r"(a[3]), "r"(b[0]), "r"(b[1]));
}

// ---------------------------------------------------------------------------
// Kernel 0: zero pooled scratch
// ---------------------------------------------------------------------------
__global__ void zero_pooled() {
    const size_t total = (size_t)B_SZ * N_OUT * CCH / 4;
    float4 z = make_float4(0.f, 0.f, 0.f, 0.f);
    float4* p = reinterpret_cast<float4*>(g_pooled);
    for (size_t i = (size_t)blockIdx.x * blockDim.x + threadIdx.x; i < total;
         i += (size_t)gridDim.x * blockDim.x)
        p[i] = z;
}

// ---------------------------------------------------------------------------
// Kernel 1: sparse pool — red.global.add.v4.f32
// ---------------------------------------------------------------------------
__global__ void pool_kernel(const float* __restrict__ x,
                            const float* __restrict__ tv,
                            const int* __restrict__ tr,
                            const int* __restrict__ tc) {
    int t = blockIdx.x * blockDim.x + threadIdx.x;
    if (t >= NNZ * 16) return;
    int e  = t >> 4;
    int cg = t & 15;
    float v = __ldg(tv + e);
    int row = __ldg(tr + e);
    int col = __ldg(tc + e);
    const float4* xp = reinterpret_cast<const float4*>(x);
#pragma unroll
    for (int b = 0; b < B_SZ; b++) {
        float4 xv = xp[((size_t)b * N_IN + col) * 16 + cg];
        float* dst = g_pooled + ((size_t)b * N_OUT + row) * CCH + cg * 4;
        asm volatile("red.global.add.v4.f32 [%0], {%1, %2, %3, %4};"
                     :: "l"(dst), "f"(xv.x * v), "f"(xv.y * v),
                        "f"(xv.z * v), "f"(xv.w * v)
                     : "memory");
    }
}

// ---------------------------------------------------------------------------
// Kernel 2: split pooled fp32 -> bf16 hi + lo
// ---------------------------------------------------------------------------
__device__ __forceinline__ void split_bf16(float a, unsigned short& h,
                                           unsigned short& l) {
    __nv_bfloat16 hb = __float2bfloat16_rn(a);
    float r = a - __bfloat162float(hb);
    __nv_bfloat16 lb = __float2bfloat16_rn(r);
    h = __bfloat16_as_ushort(hb);
    l = __bfloat16_as_ushort(lb);
}

__global__ void convert_pooled() {
    const size_t total = (size_t)B_SZ * N_OUT * CCH / 4;
    const float4* src = reinterpret_cast<const float4*>(g_pooled);
    ushort4* dh = reinterpret_cast<ushort4*>(g_pooled_hi);
    ushort4* dl = reinterpret_cast<ushort4*>(g_pooled_lo);
    for (size_t i = (size_t)blockIdx.x * blockDim.x + threadIdx.x; i < total;
         i += (size_t)gridDim.x * blockDim.x) {
        float4 v = src[i];
        ushort4 h, l;
        split_bf16(v.x, h.x, l.x);
        split_bf16(v.y, h.y, l.y);
        split_bf16(v.z, h.z, l.z);
        split_bf16(v.w, h.w, l.w);
        dh[i] = h;
        dl[i] = l;
    }
}

// ---------------------------------------------------------------------------
// Kernel 3: transpose + split W -> [9][n=64][k=64] bf16 hi/lo
// ---------------------------------------------------------------------------
__global__ void wsplit_kernel(const float* __restrict__ W) {
    int s = blockIdx.x;
    int n = threadIdx.x;
    unsigned short* dh = g_wt_hi + (s * 64 + n) * 64;
    unsigned short* dl = g_wt_lo + (s * 64 + n) * 64;
#pragma unroll
    for (int k = 0; k < 64; k++) {
        float w = __ldg(W + (size_t)(s * 64 + k) * 64 + n);
        unsigned short h, l;
        split_bf16(w, h, l);
        dh[k] = h;
        dl[k] = l;
    }
}

// ---------------------------------------------------------------------------
// Kernel 4: fused spiral gather + mma.sync bf16 3-term GEMM + bias + ELU
// CTA: 128 rows x 64 cols; 256 threads = 8 warps (4x2), warp tile 32x32.
// Per slice SMEM stage (48 KB): Ah 16K | Al 16K | Bh 8K | Bl 8K. x2 buffers.
// ---------------------------------------------------------------------------
#define A_LO_OFF  16384
#define B_HI_OFF  32768
#define B_LO_OFF  40960
#define STAGE_SZ  49152
#define GEMM_SMEM (2 * STAGE_SZ)

__global__ void __launch_bounds__(256, 2) spiral_gemm_mma(
    const int*   __restrict__ sp,
    const float* __restrict__ bias,
    float*       __restrict__ out) {
    extern __shared__ char smem[];
    const uint32_t sbase = smem_u32(smem);

    const int tid = threadIdx.x;
    const int l   = tid & 31;
    const int wid = tid >> 5;
    const int wm  = wid >> 1;   // 0..3 -> m offset 32*wm
    const int wn  = wid & 1;    // 0..1 -> n offset 32*wn
    const int b   = blockIdx.y;
    const int n0  = blockIdx.x * 128;

    // staging roles
    const int arow  = tid >> 1;        // 0..127
    const int ahalf = tid & 1;         // 64B half of 128B row
    const int breg  = tid >> 7;        // 0 = hi, 1 = lo
    const int bn    = (tid & 127) >> 1;
    const int bhalf = tid & 1;

    const unsigned short* basePH = g_pooled_hi + (size_t)b * N_OUT * CCH;
    const unsigned short* basePL = g_pooled_lo + (size_t)b * N_OUT * CCH;

    float acc[2][4][4];
#pragma unroll
    for (int mi = 0; mi < 2; mi++)
#pragma unroll
        for (int nj = 0; nj < 4; nj++)
#pragma unroll
            for (int j = 0; j < 4; j++) acc[mi][nj][j] = 0.f;

    int nn = n0 + arow;
    if (nn >= N_OUT) nn = N_OUT - 1;

    // ---- staging function ----
    auto stage = [&](int s, uint32_t stg) {
        // A: gathered row, pre-split bf16, 128B hi + 128B lo per row
        int idx = __ldg(sp + (size_t)nn * SNB + s);
        const char* srcH =
            (const char*)(basePH + (size_t)idx * CCH) + ahalf * 64;
        const char* srcL =
            (const char*)(basePL + (size_t)idx * CCH) + ahalf * 64;
        uint32_t dstrow = stg + arow * 128;
        const int rx = arow & 7;
#pragma unroll
        for (int j = 0; j < 4; j++) {
            int c = ahalf * 4 + j;
            int sc = c ^ rx;
            cp16(dstrow + sc * 16, srcH + j * 16);
            cp16(dstrow + A_LO_OFF + sc * 16, srcL + j * 16);
        }
        // B: W slice, 64 rows x 128B (hi region or lo region per thread half)
        const unsigned short* wsrc =
            (breg ? g_wt_lo : g_wt_hi) + (size_t)(s * 64 + bn) * 64 +
            bhalf * 32;
        uint32_t dstB = stg + B_HI_OFF + breg * 8192 + bn * 128;
        const int bx = bn & 7;
#pragma unroll
        for (int j = 0; j < 4; j++) {
            int c = bhalf * 4 + j;
            int sc = c ^ bx;
            cp16(dstB + sc * 16, (const char*)wsrc + j * 16);
        }
        cp_commit();
    };

    // ---- compute function over one staged slice ----
    auto compute = [&](uint32_t stg) {
#pragma unroll
        for (int kk = 0; kk < 4; kk++) {
            uint32_t ah[2][4], al[2][4], bh[2][4], bl[2][4];
#pragma unroll
            for (int mi = 0; mi < 2; mi++) {
                int row = wm * 32 + mi * 16 + (l & 15);
                int c = kk * 2 + (l >> 4);
                uint32_t addr = stg + row * 128 + ((c ^ (row & 7)) << 4);
                ldm4(ah[mi], addr);
                ldm4(al[mi], addr + A_LO_OFF);
            }
#pragma unroll
            for (int np = 0; np < 2; np++) {
                int row = wn * 32 + np * 16 + (l & 7) + ((l >> 4) << 3);
                int c = kk * 2 + ((l >> 3) & 1);
                uint32_t addr =
                    stg + B_HI_OFF + row * 128 + ((c ^ (row & 7)) << 4);
                ldm4(bh[np], addr);
                ldm4(bl[np], addr + 8192);
            }
#pragma unroll
            for (int mi = 0; mi < 2; mi++)
#pragma unroll
                for (int nj = 0; nj < 4; nj++) {
                    const uint32_t* bph = &bh[nj >> 1][(nj & 1) * 2];
                    const uint32_t* bpl = &bl[nj >> 1][(nj & 1) * 2];
                    mma16816(acc[mi][nj], ah[mi], bph);
                    mma16816(acc[mi][nj], ah[mi], bpl);
                    mma16816(acc[mi][nj], al[mi], bph);
                }
        }
    };

    // ---- pipelined main loop ----
    stage(0, sbase);
    for (int s = 0; s < SNB; s++) {
        if (s + 1 < SNB) {
            stage(s + 1, sbase + ((s + 1) & 1) * STAGE_SZ);
            cp_wait<1>();
        } else {
            cp_wait<0>();
        }
        __syncthreads();
        compute(sbase + (s & 1) * STAGE_SZ);
        __syncthreads();
    }

    // ---- epilogue: bias + ELU + store ----
    float bias8[4][2];
#pragma unroll
    for (int nj = 0; nj < 4; nj++) {
        int col = wn * 32 + nj * 8 + (l & 3) * 2;
        bias8[nj][0] = __ldg(bias + col);
        bias8[nj][1] = __ldg(bias + col + 1);
    }
#pragma unroll
    for (int mi = 0; mi < 2; mi++) {
#pragma unroll
        for (int half = 0; half < 2; half++) {
            int m = wm * 32 + mi * 16 + (l >> 2) + half * 8;
            int n = n0 + m;
            if (n >= N_OUT) continue;
            float* dst = out + ((size_t)b * N_OUT + n) * CCH;
#pragma unroll
            for (int nj = 0; nj < 4; nj++) {
                int col = wn * 32 + nj * 8 + (l & 3) * 2;
                float t0 = acc[mi][nj][half * 2 + 0] + bias8[nj][0];
                float t1 = acc[mi][nj][half * 2 + 1] + bias8[nj][1];
                float2 o;
                o.x = (t0 > 0.f) ? t0 : expm1f(t0);
                o.y = (t1 > 0.f) ? t1 : expm1f(t1);
                *reinterpret_cast<float2*>(dst + col) = o;
            }
        }
    }
}

// ---------------------------------------------------------------------------
extern "C" void kernel_launch(void* const* d_in, const int* in_sizes, int n_in,
                              void* d_out, int out_size) {
    const float* x    = (const float*)d_in[0];
    const float* tv   = (const float*)d_in[1];
    const int*   tr   = (const int*)d_in[2];
    const int*   tc   = (const int*)d_in[3];
    const int*   sp   = (const int*)d_in[4];
    const float* W    = (const float*)d_in[5];
    const float* bias = (const float*)d_in[6];
    float* out = (float*)d_out;

    static bool attr_set = false;
    if (!attr_set) {
        cudaFuncSetAttribute(spiral_gemm_mma,
                             cudaFuncAttributeMaxDynamicSharedMemorySize,
                             GEMM_SMEM);
        attr_set = true;
    }

    zero_pooled<<<2048, 256>>>();
    pool_kernel<<<(NNZ * 16 + 255) / 256, 256>>>(x, tv, tr, tc);
    wsplit_kernel<<<SNB, 64>>>(W);
    convert_pooled<<<2048, 256>>>();

    dim3 grid((N_OUT + 127) / 128, B_SZ);
    spiral_gemm_mma<<<grid, 256, GEMM_SMEM>>>(sp, bias, out);
}

// round 4
// speedup vs baseline: 2.4913x; 1.4106x over previous
#include <cuda_runtime.h>
#include <cuda_fp16.h>
#include <cstdint>

#define B_SZ  16
#define N_IN  6250
#define N_OUT 25000
#define CCH   64
#define SNB   9
#define NNZ   75000

// fp32 pooled accumulator [B][N_OUT][64] = 102.4 MB
__device__ float g_pooled[(size_t)B_SZ * N_OUT * CCH];
// fp16 pooled [B][N_OUT][64] = 51.2 MB
__device__ unsigned short g_pooled_h[(size_t)B_SZ * N_OUT * CCH];
// transposed split W: [9][n=64][k=64] fp16 hi and lo
__device__ unsigned short g_wt_h[SNB * 64 * 64];
__device__ unsigned short g_wt_l[SNB * 64 * 64];

// ---------------------------------------------------------------------------
// helpers
// ---------------------------------------------------------------------------
__device__ __forceinline__ uint32_t smem_u32(const void* p) {
    uint32_t a;
    asm("{ .reg .u64 t; cvta.to.shared.u64 t, %1; cvt.u32.u64 %0, t; }"
        : "=r"(a) : "l"(p));
    return a;
}
__device__ __forceinline__ void cp16(uint32_t dst, const void* src) {
    asm volatile("cp.async.cg.shared.global [%0], [%1], 16;"
                 :: "r"(dst), "l"(src) : "memory");
}
__device__ __forceinline__ void cp_commit() {
    asm volatile("cp.async.commit_group;" ::: "memory");
}
template <int N>
__device__ __forceinline__ void cp_wait() {
    asm volatile("cp.async.wait_group %0;" :: "n"(N) : "memory");
}
__device__ __forceinline__ void ldm4(uint32_t* r, uint32_t addr) {
    asm volatile("ldmatrix.sync.aligned.m8n8.x4.shared.b16 {%0,%1,%2,%3}, [%4];"
                 : "=r"(r[0]), "=r"(r[1]), "=r"(r[2]), "=r"(r[3])
                 : "r"(addr));
}
__device__ __forceinline__ void mma16816(float* d, const uint32_t* a,
                                         const uint32_t* b) {
    asm volatile(
        "mma.sync.aligned.m16n8k16.row.col.f32.f16.f16.f32 "
        "{%0,%1,%2,%3},{%4,%5,%6,%7},{%8,%9},{%0,%1,%2,%3};"
        : "+f"(d[0]), "+f"(d[1]), "+f"(d[2]), "+f"(d[3])
        : "r"(a[0]), "r"(a[1]), "r"(a[2]), "r"(a[3]), "r"(b[0]), "r"(b[1]));
}

// ---------------------------------------------------------------------------
// Kernel 0: zero pooled scratch
// ---------------------------------------------------------------------------
__global__ void zero_pooled() {
    const size_t total = (size_t)B_SZ * N_OUT * CCH / 4;
    float4 z = make_float4(0.f, 0.f, 0.f, 0.f);
    float4* p = reinterpret_cast<float4*>(g_pooled);
    for (size_t i = (size_t)blockIdx.x * blockDim.x + threadIdx.x; i < total;
         i += (size_t)gridDim.x * blockDim.x)
        p[i] = z;
}

// ---------------------------------------------------------------------------
// Kernel 1: sparse pool — red.global.add.v4.f32
// ---------------------------------------------------------------------------
__global__ void pool_kernel(const float* __restrict__ x,
                            const float* __restrict__ tv,
                            const int* __restrict__ tr,
                            const int* __restrict__ tc) {
    int t = blockIdx.x * blockDim.x + threadIdx.x;
    if (t >= NNZ * 16) return;
    int e  = t >> 4;
    int cg = t & 15;
    float v = __ldg(tv + e);
    int row = __ldg(tr + e);
    int col = __ldg(tc + e);
    const float4* xp = reinterpret_cast<const float4*>(x);
#pragma unroll
    for (int b = 0; b < B_SZ; b++) {
        float4 xv = xp[((size_t)b * N_IN + col) * 16 + cg];
        float* dst = g_pooled + ((size_t)b * N_OUT + row) * CCH + cg * 4;
        asm volatile("red.global.add.v4.f32 [%0], {%1, %2, %3, %4};"
                     :: "l"(dst), "f"(xv.x * v), "f"(xv.y * v),
                        "f"(xv.z * v), "f"(xv.w * v)
                     : "memory");
    }
}

// ---------------------------------------------------------------------------
// Kernel 2: convert pooled fp32 -> fp16 (single quantization of A)
// ---------------------------------------------------------------------------
__global__ void convert_pooled() {
    const size_t total = (size_t)B_SZ * N_OUT * CCH / 4;
    const float4* src = reinterpret_cast<const float4*>(g_pooled);
    ushort4* dh = reinterpret_cast<ushort4*>(g_pooled_h);
    for (size_t i = (size_t)blockIdx.x * blockDim.x + threadIdx.x; i < total;
         i += (size_t)gridDim.x * blockDim.x) {
        float4 v = src[i];
        ushort4 h;
        h.x = __half_as_ushort(__float2half_rn(v.x));
        h.y = __half_as_ushort(__float2half_rn(v.y));
        h.z = __half_as_ushort(__float2half_rn(v.z));
        h.w = __half_as_ushort(__float2half_rn(v.w));
        dh[i] = h;
    }
}

// ---------------------------------------------------------------------------
// Kernel 3: transpose + split W -> [9][n=64][k=64] fp16 hi/lo (w = wh + wl)
// ---------------------------------------------------------------------------
__global__ void wsplit_kernel(const float* __restrict__ W) {
    int s = blockIdx.x;
    int n = threadIdx.x;
    unsigned short* dh = g_wt_h + (s * 64 + n) * 64;
    unsigned short* dl = g_wt_l + (s * 64 + n) * 64;
#pragma unroll
    for (int k = 0; k < 64; k++) {
        float w = __ldg(W + (size_t)(s * 64 + k) * 64 + n);
        __half wh = __float2half_rn(w);
        __half wl = __float2half_rn(w - __half2float(wh));
        dh[k] = __half_as_ushort(wh);
        dl[k] = __half_as_ushort(wl);
    }
}

// ---------------------------------------------------------------------------
// Kernel 4: fused spiral gather + fp16 2-product GEMM + bias + ELU
// CTA: 128 rows x 64 cols; 256 threads = 8 warps (4x2), warp tile 32x32.
// Stage (32 KB): A 16K | Wh 8K | Wl 8K.  3-stage ring, 1 sync/slice.
// ---------------------------------------------------------------------------
#define B_HI_OFF  16384
#define STAGE_SZ  32768
#define NSTAGE    3
#define GEMM_SMEM (NSTAGE * STAGE_SZ)

__global__ void __launch_bounds__(256, 2) spiral_gemm_mma(
    const int*   __restrict__ sp,
    const float* __restrict__ bias,
    float*       __restrict__ out) {
    extern __shared__ char smem[];
    const uint32_t sbase = smem_u32(smem);

    const int tid = threadIdx.x;
    const int l   = tid & 31;
    const int wid = tid >> 5;
    const int wm  = wid >> 1;   // m offset 32*wm
    const int wn  = wid & 1;    // n offset 32*wn
    const int b   = blockIdx.y;
    const int n0  = blockIdx.x * 128;

    // staging roles: 2 threads per 128B row, for A (128 rows) and B (128 rows)
    const int arow  = tid >> 1;
    const int ahalf = tid & 1;
    const int brow  = tid >> 1;        // 0..63 -> Wh row, 64..127 -> Wl row
    const int bhalf = tid & 1;

    const unsigned short* basePH = g_pooled_h + (size_t)b * N_OUT * CCH;

    float acc[2][4][4];
#pragma unroll
    for (int mi = 0; mi < 2; mi++)
#pragma unroll
        for (int nj = 0; nj < 4; nj++)
#pragma unroll
            for (int j = 0; j < 4; j++) acc[mi][nj][j] = 0.f;

    int nn = n0 + arow;
    if (nn >= N_OUT) nn = N_OUT - 1;

    // prefetch spiral indices
    int sidx[SNB];
#pragma unroll
    for (int s = 0; s < SNB; s++) sidx[s] = __ldg(sp + (size_t)nn * SNB + s);

    const unsigned short* wsrcBase =
        (brow < 64) ? g_wt_h : g_wt_l;
    const int brmod = brow & 63;

    auto stage = [&](int s) {
        const uint32_t stg = sbase + (s % NSTAGE) * STAGE_SZ;
        // A: gathered row, fp16, 128B per row
        const char* srcA =
            (const char*)(basePH + (size_t)sidx[s] * CCH) + ahalf * 64;
        uint32_t dstA = stg + arow * 128;
        const int rx = arow & 7;
#pragma unroll
        for (int j = 0; j < 4; j++) {
            int c = ahalf * 4 + j;
            cp16(dstA + ((c ^ rx) << 4), srcA + j * 16);
        }
        // B: Wh rows 0..63 then Wl rows 64..127, 128B per row
        const char* srcB =
            (const char*)(wsrcBase + (size_t)(s * 64 + brmod) * 64) +
            bhalf * 64;
        uint32_t dstB = stg + B_HI_OFF + brow * 128;
        const int bx = brow & 7;
#pragma unroll
        for (int j = 0; j < 4; j++) {
            int c = bhalf * 4 + j;
            cp16(dstB + ((c ^ bx) << 4), srcB + j * 16);
        }
        cp_commit();
    };

    auto compute = [&](int s) {
        const uint32_t stg = sbase + (s % NSTAGE) * STAGE_SZ;
#pragma unroll
        for (int kk = 0; kk < 4; kk++) {
            uint32_t ah[2][4], bh[2][4], bl[2][4];
#pragma unroll
            for (int mi = 0; mi < 2; mi++) {
                int row = wm * 32 + mi * 16 + (l & 15);
                int c = kk * 2 + (l >> 4);
                ldm4(ah[mi], stg + row * 128 + ((c ^ (row & 7)) << 4));
            }
#pragma unroll
            for (int np = 0; np < 2; np++) {
                int row = wn * 32 + np * 16 + (l & 7) + ((l >> 4) << 3);
                int c = kk * 2 + ((l >> 3) & 1);
                uint32_t addr =
                    stg + B_HI_OFF + row * 128 + ((c ^ (row & 7)) << 4);
                ldm4(bh[np], addr);
                ldm4(bl[np], addr + 8192);
            }
            // term-major: all 8 accs on Wh, then all 8 on Wl (ILP spacing)
#pragma unroll
            for (int mi = 0; mi < 2; mi++)
#pragma unroll
                for (int nj = 0; nj < 4; nj++)
                    mma16816(acc[mi][nj], ah[mi], &bh[nj >> 1][(nj & 1) * 2]);
#pragma unroll
            for (int mi = 0; mi < 2; mi++)
#pragma unroll
                for (int nj = 0; nj < 4; nj++)
                    mma16816(acc[mi][nj], ah[mi], &bl[nj >> 1][(nj & 1) * 2]);
        }
    };

    // ---- 3-stage pipelined main loop, one sync per slice ----
    stage(0);
    stage(1);
#pragma unroll
    for (int s = 0; s < SNB; s++) {
        cp_wait<1>();          // slice s resident (s+1 may still be in flight)
        __syncthreads();
        if (s + 2 < SNB) stage(s + 2);
        else cp_commit();      // keep group count aligned for cp_wait<1>
        compute(s);
    }

    // ---- epilogue: bias + ELU + store ----
    float bias8[4][2];
#pragma unroll
    for (int nj = 0; nj < 4; nj++) {
        int col = wn * 32 + nj * 8 + (l & 3) * 2;
        bias8[nj][0] = __ldg(bias + col);
        bias8[nj][1] = __ldg(bias + col + 1);
    }
#pragma unroll
    for (int mi = 0; mi < 2; mi++) {
#pragma unroll
        for (int half = 0; half < 2; half++) {
            int m = wm * 32 + mi * 16 + (l >> 2) + half * 8;
            int n = n0 + m;
            if (n >= N_OUT) continue;
            float* dst = out + ((size_t)b * N_OUT + n) * CCH;
#pragma unroll
            for (int nj = 0; nj < 4; nj++) {
                int col = wn * 32 + nj * 8 + (l & 3) * 2;
                float t0 = acc[mi][nj][half * 2 + 0] + bias8[nj][0];
                float t1 = acc[mi][nj][half * 2 + 1] + bias8[nj][1];
                float2 o;
                o.x = (t0 > 0.f) ? t0 : expm1f(t0);
                o.y = (t1 > 0.f) ? t1 : expm1f(t1);
                *reinterpret_cast<float2*>(dst + col) = o;
            }
        }
    }
}

// ---------------------------------------------------------------------------
extern "C" void kernel_launch(void* const* d_in, const int* in_sizes, int n_in,
                              void* d_out, int out_size) {
    const float* x    = (const float*)d_in[0];
    const float* tv   = (const float*)d_in[1];
    const int*   tr   = (const int*)d_in[2];
    const int*   tc   = (const int*)d_in[3];
    const int*   sp   = (const int*)d_in[4];
    const float* W    = (const float*)d_in[5];
    const float* bias = (const float*)d_in[6];
    float* out = (float*)d_out;

    static bool attr_set = false;
    if (!attr_set) {
        cudaFuncSetAttribute(spiral_gemm_mma,
                             cudaFuncAttributeMaxDynamicSharedMemorySize,
                             GEMM_SMEM);
        attr_set = true;
    }

    zero_pooled<<<2048, 256>>>();
    pool_kernel<<<(NNZ * 16 + 255) / 256, 256>>>(x, tv, tr, tc);
    wsplit_kernel<<<SNB, 64>>>(W);
    convert_pooled<<<2048, 256>>>();

    dim3 grid((N_OUT + 127) / 128, B_SZ);
    spiral_gemm_mma<<<grid, 256, GEMM_SMEM>>>(sp, bias, out);
}

// round 5
// speedup vs baseline: 2.8193x; 1.1316x over previous
#include <cuda_runtime.h>
#include <cuda_fp16.h>
#include <cstdint>

#define B_SZ  16
#define N_IN  6250
#define N_OUT 25000
#define CCH   64
#define SNB   9
#define NNZ   75000

// fp16 pooled [B][N_OUT][64] = 51.2 MB (written directly by pool_gather)
__device__ unsigned short g_pooled_h[(size_t)B_SZ * N_OUT * CCH];
// transposed split W: [9][n=64][k=64] fp16 hi and lo
__device__ unsigned short g_wt_h[SNB * 64 * 64];
__device__ unsigned short g_wt_l[SNB * 64 * 64];
// CSR scratch for the sparse pool
__device__ int   g_cnt[N_OUT];
__device__ int   g_off[N_OUT + 1];
__device__ int   g_cur[N_OUT];
__device__ int   g_ecol[NNZ];
__device__ float g_eval[NNZ];

// ---------------------------------------------------------------------------
// helpers
// ---------------------------------------------------------------------------
__device__ __forceinline__ uint32_t smem_u32(const void* p) {
    uint32_t a;
    asm("{ .reg .u64 t; cvta.to.shared.u64 t, %1; cvt.u32.u64 %0, t; }"
        : "=r"(a) : "l"(p));
    return a;
}
__device__ __forceinline__ void cp16(uint32_t dst, const void* src) {
    asm volatile("cp.async.cg.shared.global [%0], [%1], 16;"
                 :: "r"(dst), "l"(src) : "memory");
}
__device__ __forceinline__ void cp_commit() {
    asm volatile("cp.async.commit_group;" ::: "memory");
}
template <int N>
__device__ __forceinline__ void cp_wait() {
    asm volatile("cp.async.wait_group %0;" :: "n"(N) : "memory");
}
__device__ __forceinline__ void ldm4(uint32_t* r, uint32_t addr) {
    asm volatile("ldmatrix.sync.aligned.m8n8.x4.shared.b16 {%0,%1,%2,%3}, [%4];"
                 : "=r"(r[0]), "=r"(r[1]), "=r"(r[2]), "=r"(r[3])
                 : "r"(addr));
}
__device__ __forceinline__ void mma16816(float* d, const uint32_t* a,
                                         const uint32_t* b) {
    asm volatile(
        "mma.sync.aligned.m16n8k16.row.col.f32.f16.f16.f32 "
        "{%0,%1,%2,%3},{%4,%5,%6,%7},{%8,%9},{%0,%1,%2,%3};"
        : "+f"(d[0]), "+f"(d[1]), "+f"(d[2]), "+f"(d[3])
        : "r"(a[0]), "r"(a[1]), "r"(a[2]), "r"(a[3]), "r"(b[0]), "r"(b[1]));
}

// ---------------------------------------------------------------------------
// CSR build: zero -> hist -> scan -> scatter
// ---------------------------------------------------------------------------
__global__ void csr_zero() {
    int t = blockIdx.x * blockDim.x + threadIdx.x;
    if (t < N_OUT) g_cnt[t] = 0;
}

__global__ void csr_hist(const int* __restrict__ tr) {
    int t = blockIdx.x * blockDim.x + threadIdx.x;
    if (t < NNZ) atomicAdd(&g_cnt[__ldg(tr + t)], 1);
}

#define SCAN_T 1024
#define ROWS_PER_T 25   // 1024 * 25 = 25600 >= 25000
__global__ void __launch_bounds__(SCAN_T) csr_scan() {
    __shared__ int s[SCAN_T];
    const int t = threadIdx.x;
    const int base = t * ROWS_PER_T;
    int local[ROWS_PER_T];
    int sum = 0;
#pragma unroll
    for (int i = 0; i < ROWS_PER_T; i++) {
        int r = base + i;
        local[i] = (r < N_OUT) ? g_cnt[r] : 0;
        sum += local[i];
    }
    s[t] = sum;
    __syncthreads();
    // Hillis-Steele inclusive scan
    for (int ofs = 1; ofs < SCAN_T; ofs <<= 1) {
        int v = (t >= ofs) ? s[t - ofs] : 0;
        __syncthreads();
        s[t] += v;
        __syncthreads();
    }
    int run = s[t] - sum;   // exclusive prefix
#pragma unroll
    for (int i = 0; i < ROWS_PER_T; i++) {
        int r = base + i;
        if (r < N_OUT) {
            g_off[r] = run;
            g_cur[r] = run;
            run += local[i];
        }
    }
    if (t == SCAN_T - 1) g_off[N_OUT] = NNZ;
}

__global__ void csr_scatter(const float* __restrict__ tv,
                            const int* __restrict__ tr,
                            const int* __restrict__ tc) {
    int t = blockIdx.x * blockDim.x + threadIdx.x;
    if (t >= NNZ) return;
    int row = __ldg(tr + t);
    int pos = atomicAdd(&g_cur[row], 1);
    g_ecol[pos] = __ldg(tc + t);
    g_eval[pos] = __ldg(tv + t);
}

// ---------------------------------------------------------------------------
// pool_gather: one warp per output row. lane = cg (0..15) x bhalf (0..1).
// Accumulate fp32 in registers over the row's CSR entries, store fp16.
// ---------------------------------------------------------------------------
__global__ void __launch_bounds__(256) pool_gather(const float* __restrict__ x) {
    int t = blockIdx.x * blockDim.x + threadIdx.x;
    if (t >= N_OUT * 32) return;
    const int row = t >> 5;
    const int r   = t & 31;
    const int cg  = r & 15;        // float4 channel group
    const int b0  = (r >> 4) * 8;  // batch half: 0..7 or 8..15

    const int start = g_off[row];
    const int end   = g_off[row + 1];

    float4 acc[8];
#pragma unroll
    for (int b = 0; b < 8; b++) acc[b] = make_float4(0.f, 0.f, 0.f, 0.f);

    const float4* xp = reinterpret_cast<const float4*>(x);
    for (int i = start; i < end; i++) {
        int col = __ldg(g_ecol + i);
        float v = __ldg(g_eval + i);
        const float4* src = xp + ((size_t)b0 * N_IN + col) * 16 + cg;
#pragma unroll
        for (int b = 0; b < 8; b++) {
            float4 xv = src[(size_t)b * N_IN * 16];
            acc[b].x += v * xv.x;
            acc[b].y += v * xv.y;
            acc[b].z += v * xv.z;
            acc[b].w += v * xv.w;
        }
    }
#pragma unroll
    for (int b = 0; b < 8; b++) {
        ushort4 h;
        h.x = __half_as_ushort(__float2half_rn(acc[b].x));
        h.y = __half_as_ushort(__float2half_rn(acc[b].y));
        h.z = __half_as_ushort(__float2half_rn(acc[b].z));
        h.w = __half_as_ushort(__float2half_rn(acc[b].w));
        *reinterpret_cast<ushort4*>(
            g_pooled_h + ((size_t)(b0 + b) * N_OUT + row) * CCH + cg * 4) = h;
    }
}

// ---------------------------------------------------------------------------
// wsplit: transpose + split W -> [9][n=64][k=64] fp16 hi/lo (w = wh + wl)
// ---------------------------------------------------------------------------
__global__ void wsplit_kernel(const float* __restrict__ W) {
    int s = blockIdx.x;
    int n = threadIdx.x;
    unsigned short* dh = g_wt_h + (s * 64 + n) * 64;
    unsigned short* dl = g_wt_l + (s * 64 + n) * 64;
#pragma unroll
    for (int k = 0; k < 64; k++) {
        float w = __ldg(W + (size_t)(s * 64 + k) * 64 + n);
        __half wh = __float2half_rn(w);
        __half wl = __float2half_rn(w - __half2float(wh));
        dh[k] = __half_as_ushort(wh);
        dl[k] = __half_as_ushort(wl);
    }
}

// ---------------------------------------------------------------------------
// fused spiral gather + fp16 2-product GEMM + bias + ELU
// CTA: 128 rows x 64 cols; 256 threads = 8 warps (4x2), warp tile 32x32.
// Stage (32 KB): A 16K | Wh 8K | Wl 8K.  3-stage ring, 1 sync/slice.
// ---------------------------------------------------------------------------
#define B_HI_OFF  16384
#define STAGE_SZ  32768
#define NSTAGE    3
#define GEMM_SMEM (NSTAGE * STAGE_SZ)

__global__ void __launch_bounds__(256, 2) spiral_gemm_mma(
    const int*   __restrict__ sp,
    const float* __restrict__ bias,
    float*       __restrict__ out) {
    extern __shared__ char smem[];
    const uint32_t sbase = smem_u32(smem);

    const int tid = threadIdx.x;
    const int l   = tid & 31;
    const int wid = tid >> 5;
    const int wm  = wid >> 1;
    const int wn  = wid & 1;
    const int b   = blockIdx.y;
    const int n0  = blockIdx.x * 128;

    const int arow  = tid >> 1;
    const int ahalf = tid & 1;
    const int brow  = tid >> 1;
    const int bhalf = tid & 1;

    const unsigned short* basePH = g_pooled_h + (size_t)b * N_OUT * CCH;

    float acc[2][4][4];
#pragma unroll
    for (int mi = 0; mi < 2; mi++)
#pragma unroll
        for (int nj = 0; nj < 4; nj++)
#pragma unroll
            for (int j = 0; j < 4; j++) acc[mi][nj][j] = 0.f;

    int nn = n0 + arow;
    if (nn >= N_OUT) nn = N_OUT - 1;

    int sidx[SNB];
#pragma unroll
    for (int s = 0; s < SNB; s++) sidx[s] = __ldg(sp + (size_t)nn * SNB + s);

    const unsigned short* wsrcBase = (brow < 64) ? g_wt_h : g_wt_l;
    const int brmod = brow & 63;

    auto stage = [&](int s) {
        const uint32_t stg = sbase + (s % NSTAGE) * STAGE_SZ;
        const char* srcA =
            (const char*)(basePH + (size_t)sidx[s] * CCH) + ahalf * 64;
        uint32_t dstA = stg + arow * 128;
        const int rx = arow & 7;
#pragma unroll
        for (int j = 0; j < 4; j++) {
            int c = ahalf * 4 + j;
            cp16(dstA + ((c ^ rx) << 4), srcA + j * 16);
        }
        const char* srcB =
            (const char*)(wsrcBase + (size_t)(s * 64 + brmod) * 64) +
            bhalf * 64;
        uint32_t dstB = stg + B_HI_OFF + brow * 128;
        const int bx = brow & 7;
#pragma unroll
        for (int j = 0; j < 4; j++) {
            int c = bhalf * 4 + j;
            cp16(dstB + ((c ^ bx) << 4), srcB + j * 16);
        }
        cp_commit();
    };

    auto compute = [&](int s) {
        const uint32_t stg = sbase + (s % NSTAGE) * STAGE_SZ;
#pragma unroll
        for (int kk = 0; kk < 4; kk++) {
            uint32_t ah[2][4], bh[2][4], bl[2][4];
#pragma unroll
            for (int mi = 0; mi < 2; mi++) {
                int row = wm * 32 + mi * 16 + (l & 15);
                int c = kk * 2 + (l >> 4);
                ldm4(ah[mi], stg + row * 128 + ((c ^ (row & 7)) << 4));
            }
#pragma unroll
            for (int np = 0; np < 2; np++) {
                int row = wn * 32 + np * 16 + (l & 7) + ((l >> 4) << 3);
                int c = kk * 2 + ((l >> 3) & 1);
                uint32_t addr =
                    stg + B_HI_OFF + row * 128 + ((c ^ (row & 7)) << 4);
                ldm4(bh[np], addr);
                ldm4(bl[np], addr + 8192);
            }
#pragma unroll
            for (int mi = 0; mi < 2; mi++)
#pragma unroll
                for (int nj = 0; nj < 4; nj++)
                    mma16816(acc[mi][nj], ah[mi], &bh[nj >> 1][(nj & 1) * 2]);
#pragma unroll
            for (int mi = 0; mi < 2; mi++)
#pragma unroll
                for (int nj = 0; nj < 4; nj++)
                    mma16816(acc[mi][nj], ah[mi], &bl[nj >> 1][(nj & 1) * 2]);
        }
    };

    stage(0);
    stage(1);
#pragma unroll
    for (int s = 0; s < SNB; s++) {
        cp_wait<1>();
        __syncthreads();
        if (s + 2 < SNB) stage(s + 2);
        else cp_commit();
        compute(s);
    }

    float bias8[4][2];
#pragma unroll
    for (int nj = 0; nj < 4; nj++) {
        int col = wn * 32 + nj * 8 + (l & 3) * 2;
        bias8[nj][0] = __ldg(bias + col);
        bias8[nj][1] = __ldg(bias + col + 1);
    }
#pragma unroll
    for (int mi = 0; mi < 2; mi++) {
#pragma unroll
        for (int half = 0; half < 2; half++) {
            int m = wm * 32 + mi * 16 + (l >> 2) + half * 8;
            int n = n0 + m;
            if (n >= N_OUT) continue;
            float* dst = out + ((size_t)b * N_OUT + n) * CCH;
#pragma unroll
            for (int nj = 0; nj < 4; nj++) {
                int col = wn * 32 + nj * 8 + (l & 3) * 2;
                float t0 = acc[mi][nj][half * 2 + 0] + bias8[nj][0];
                float t1 = acc[mi][nj][half * 2 + 1] + bias8[nj][1];
                float2 o;
                o.x = (t0 > 0.f) ? t0 : expm1f(t0);
                o.y = (t1 > 0.f) ? t1 : expm1f(t1);
                *reinterpret_cast<float2*>(dst + col) = o;
            }
        }
    }
}

// ---------------------------------------------------------------------------
extern "C" void kernel_launch(void* const* d_in, const int* in_sizes, int n_in,
                              void* d_out, int out_size) {
    const float* x    = (const float*)d_in[0];
    const float* tv   = (const float*)d_in[1];
    const int*   tr   = (const int*)d_in[2];
    const int*   tc   = (const int*)d_in[3];
    const int*   sp   = (const int*)d_in[4];
    const float* W    = (const float*)d_in[5];
    const float* bias = (const float*)d_in[6];
    float* out = (float*)d_out;

    static bool attr_set = false;
    if (!attr_set) {
        cudaFuncSetAttribute(spiral_gemm_mma,
                             cudaFuncAttributeMaxDynamicSharedMemorySize,
                             GEMM_SMEM);
        attr_set = true;
    }

    csr_zero<<<(N_OUT + 255) / 256, 256>>>();
    csr_hist<<<(NNZ + 255) / 256, 256>>>(tr);
    csr_scan<<<1, SCAN_T>>>();
    csr_scatter<<<(NNZ + 255) / 256, 256>>>(tv, tr, tc);
    wsplit_kernel<<<SNB, 64>>>(W);
    pool_gather<<<(N_OUT * 32 + 255) / 256, 256>>>(x);

    dim3 grid((N_OUT + 127) / 128, B_SZ);
    spiral_gemm_mma<<<grid, 256, GEMM_SMEM>>>(sp, bias, out);
}